// round 6
// baseline (speedup 1.0000x reference)
#include <cuda_runtime.h>
#include <cstdint>

// out[src] += feat[dst] * w    ; feat [N,64] f32, E=1e6, N=1e5
// 4-launch CSR pipeline: hist -> fused decoupled scan -> scatter -> accum.
//
// Inputs: d_in[0]=feat f32[N*64], d_in[1]=ew f32[E],
//         d_in[2]=esrc i32[E],    d_in[3]=edst i32[E]

#define MAXN 100000
#define MAXE 1000000
#define SCAN_CHUNK 1024
#define MAXNB 128   // ceil(MAXN/1024) = 98

__device__ int    g_cnt[MAXN];        // zero at entry (zero-init; k_scan resets)
__device__ int    g_start[MAXN + 1];
__device__ int    g_cursor[MAXN];
__device__ float2 g_edge[MAXE];       // .x = __int_as_float(dst), .y = w
__device__ volatile int g_agg[MAXNB];
__device__ volatile int g_flag[MAXNB];

__global__ void k_hist(const int4* __restrict__ esrc4, int n_edges4) {
    int i = blockIdx.x * blockDim.x + threadIdx.x;
    if (i < MAXNB) g_flag[i] = 0;
    if (i < n_edges4) {
        int4 s = __ldg(&esrc4[i]);
        atomicAdd(&g_cnt[s.x], 1);
        atomicAdd(&g_cnt[s.y], 1);
        atomicAdd(&g_cnt[s.z], 1);
        atomicAdd(&g_cnt[s.w], 1);
    }
}

// grid = nb (<=98, all resident -> spin deadlock-free). Chunk scan via shuffles;
// cross-chunk decoupled prefix via fenced aggregates. Resets g_cnt inline.
__global__ __launch_bounds__(SCAN_CHUNK) void k_scan(int n) {
    __shared__ int warp_sum[32];
    __shared__ int s_pref;
    int b = blockIdx.x, t = threadIdx.x;
    int lane = t & 31, w = t >> 5;
    int i = b * SCAN_CHUNK + t;

    int v = 0;
    if (i < n) { v = g_cnt[i]; g_cnt[i] = 0; }

    int x = v;
    #pragma unroll
    for (int off = 1; off < 32; off <<= 1) {
        int y = __shfl_up_sync(0xffffffff, x, off);
        if (lane >= off) x += y;
    }
    if (lane == 31) warp_sum[w] = x;
    if (t == 0) s_pref = 0;
    __syncthreads();

    if (w == 0) {
        int ws = warp_sum[lane];
        int z = ws;
        #pragma unroll
        for (int off = 1; off < 32; off <<= 1) {
            int y = __shfl_up_sync(0xffffffff, z, off);
            if (lane >= off) z += y;
        }
        warp_sum[lane] = z - ws;
        if (lane == 31) {
            g_agg[b] = z;
            __threadfence();
            g_flag[b] = 1;
        }
    }
    __syncthreads();

    if (t < b) {
        while (g_flag[t] == 0) { }
        atomicAdd(&s_pref, g_agg[t]);
    }
    __syncthreads();
    int P = s_pref;

    if (i < n) {
        int start = P + warp_sum[w] + (x - v);
        g_start[i]  = start;
        g_cursor[i] = start;
        if (i == n - 1) g_start[n] = start + v;
    }
}

// 4 edges per thread, vectorized index/weight loads.
__global__ void k_scatter(const int4* __restrict__ esrc4,
                          const int4* __restrict__ edst4,
                          const float4* __restrict__ ew4,
                          int n_edges4) {
    int i = blockIdx.x * blockDim.x + threadIdx.x;
    if (i >= n_edges4) return;
    int4   s = __ldg(&esrc4[i]);
    int4   d = __ldg(&edst4[i]);
    float4 w = __ldg(&ew4[i]);
    int p0 = atomicAdd(&g_cursor[s.x], 1);
    int p1 = atomicAdd(&g_cursor[s.y], 1);
    int p2 = atomicAdd(&g_cursor[s.z], 1);
    int p3 = atomicAdd(&g_cursor[s.w], 1);
    g_edge[p0] = make_float2(__int_as_float(d.x), w.x);
    g_edge[p1] = make_float2(__int_as_float(d.y), w.y);
    g_edge[p2] = make_float2(__int_as_float(d.z), w.z);
    g_edge[p3] = make_float2(__int_as_float(d.w), w.w);
}

// 16 lanes per node; 4-edge software pipeline to raise gather MLP.
__global__ __launch_bounds__(256) void k_accum(const float* __restrict__ feat,
                                               float* __restrict__ out,
                                               int n_nodes) {
    int gid  = blockIdx.x * blockDim.x + threadIdx.x;
    int node = gid >> 4;
    int lane = gid & 15;
    if (node >= n_nodes) return;

    int beg = __ldg(&g_start[node]);
    int end = __ldg(&g_start[node + 1]);

    float4 acc = make_float4(0.f, 0.f, 0.f, 0.f);
    int j = beg;

    for (; j + 3 < end; j += 4) {
        // all edge loads first, then all gathers -> 4 feat loads in flight
        float2 e0 = __ldg(&g_edge[j]);
        float2 e1 = __ldg(&g_edge[j + 1]);
        float2 e2 = __ldg(&g_edge[j + 2]);
        float2 e3 = __ldg(&g_edge[j + 3]);
        const float4* r0 = reinterpret_cast<const float4*>(feat + (__float_as_int(e0.x) << 6));
        const float4* r1 = reinterpret_cast<const float4*>(feat + (__float_as_int(e1.x) << 6));
        const float4* r2 = reinterpret_cast<const float4*>(feat + (__float_as_int(e2.x) << 6));
        const float4* r3 = reinterpret_cast<const float4*>(feat + (__float_as_int(e3.x) << 6));
        float4 v0 = __ldg(&r0[lane]);
        float4 v1 = __ldg(&r1[lane]);
        float4 v2 = __ldg(&r2[lane]);
        float4 v3 = __ldg(&r3[lane]);
        acc.x += v0.x * e0.y + v1.x * e1.y + v2.x * e2.y + v3.x * e3.y;
        acc.y += v0.y * e0.y + v1.y * e1.y + v2.y * e2.y + v3.y * e3.y;
        acc.z += v0.z * e0.y + v1.z * e1.y + v2.z * e2.y + v3.z * e3.y;
        acc.w += v0.w * e0.y + v1.w * e1.y + v2.w * e2.y + v3.w * e3.y;
    }
    if (j + 1 < end) {
        float2 e0 = __ldg(&g_edge[j]);
        float2 e1 = __ldg(&g_edge[j + 1]);
        const float4* r0 = reinterpret_cast<const float4*>(feat + (__float_as_int(e0.x) << 6));
        const float4* r1 = reinterpret_cast<const float4*>(feat + (__float_as_int(e1.x) << 6));
        float4 v0 = __ldg(&r0[lane]);
        float4 v1 = __ldg(&r1[lane]);
        acc.x += v0.x * e0.y + v1.x * e1.y;
        acc.y += v0.y * e0.y + v1.y * e1.y;
        acc.z += v0.z * e0.y + v1.z * e1.y;
        acc.w += v0.w * e0.y + v1.w * e1.y;
        j += 2;
    }
    if (j < end) {
        float2 e0 = __ldg(&g_edge[j]);
        const float4* r0 = reinterpret_cast<const float4*>(feat + (__float_as_int(e0.x) << 6));
        float4 v0 = __ldg(&r0[lane]);
        acc.x += v0.x * e0.y;
        acc.y += v0.y * e0.y;
        acc.z += v0.z * e0.y;
        acc.w += v0.w * e0.y;
    }
    reinterpret_cast<float4*>(out + ((long long)node << 6))[lane] = acc;
}

extern "C" void kernel_launch(void* const* d_in, const int* in_sizes, int n_in,
                              void* d_out, int out_size)
{
    const float* feat = (const float*)d_in[0];
    const float* ew   = (const float*)d_in[1];
    const int*   esrc = (const int*)d_in[2];
    const int*   edst = (const int*)d_in[3];
    float*       out  = (float*)d_out;

    int n_edges  = in_sizes[1];
    int n_nodes  = out_size / 64;
    int nb       = (n_nodes + SCAN_CHUNK - 1) / SCAN_CHUNK;   // 98
    int n_edges4 = n_edges / 4;                               // E divisible by 4

    k_hist<<<(n_edges4 + 255) / 256, 256>>>((const int4*)esrc, n_edges4);
    k_scan<<<nb, SCAN_CHUNK>>>(n_nodes);
    k_scatter<<<(n_edges4 + 255) / 256, 256>>>((const int4*)esrc, (const int4*)edst,
                                               (const float4*)ew, n_edges4);

    long long total = (long long)n_nodes * 16;
    k_accum<<<(int)((total + 255) / 256), 256>>>(feat, out, n_nodes);
}

// round 7
// speedup vs baseline: 1.0623x; 1.0623x over previous
#include <cuda_runtime.h>
#include <cstdint>

// out[src] += feat[dst] * w    ; feat [N,64] f32, E=1e6, N=1e5
// 4-launch CSR pipeline: hist -> fused decoupled scan -> scatter -> accum.
//
// Inputs: d_in[0]=feat f32[N*64], d_in[1]=ew f32[E],
//         d_in[2]=esrc i32[E],    d_in[3]=edst i32[E]

#define MAXN 100000
#define MAXE 1000000
#define SCAN_CHUNK 1024
#define MAXNB 128   // ceil(MAXN/1024) = 98

__device__ int    g_cnt[MAXN];        // zero at entry (zero-init; k_scan resets)
__device__ int    g_start[MAXN + 1];
__device__ int    g_cursor[MAXN];
__device__ float2 g_edge[MAXE];       // .x = __int_as_float(dst), .y = w
__device__ volatile int g_agg[MAXNB];
__device__ volatile int g_flag[MAXNB];

__global__ void k_hist(const int4* __restrict__ esrc4, int n_edges4) {
    int i = blockIdx.x * blockDim.x + threadIdx.x;
    if (i < MAXNB) g_flag[i] = 0;
    if (i < n_edges4) {
        int4 s = __ldg(&esrc4[i]);
        atomicAdd(&g_cnt[s.x], 1);
        atomicAdd(&g_cnt[s.y], 1);
        atomicAdd(&g_cnt[s.z], 1);
        atomicAdd(&g_cnt[s.w], 1);
    }
}

// grid = nb (<=98, all resident -> spin deadlock-free). Chunk scan via shuffles;
// cross-chunk decoupled prefix via fenced aggregates. Resets g_cnt inline.
__global__ __launch_bounds__(SCAN_CHUNK) void k_scan(int n) {
    __shared__ int warp_sum[32];
    __shared__ int s_pref;
    int b = blockIdx.x, t = threadIdx.x;
    int lane = t & 31, w = t >> 5;
    int i = b * SCAN_CHUNK + t;

    int v = 0;
    if (i < n) { v = g_cnt[i]; g_cnt[i] = 0; }

    int x = v;
    #pragma unroll
    for (int off = 1; off < 32; off <<= 1) {
        int y = __shfl_up_sync(0xffffffff, x, off);
        if (lane >= off) x += y;
    }
    if (lane == 31) warp_sum[w] = x;
    if (t == 0) s_pref = 0;
    __syncthreads();

    if (w == 0) {
        int ws = warp_sum[lane];
        int z = ws;
        #pragma unroll
        for (int off = 1; off < 32; off <<= 1) {
            int y = __shfl_up_sync(0xffffffff, z, off);
            if (lane >= off) z += y;
        }
        warp_sum[lane] = z - ws;
        if (lane == 31) {
            g_agg[b] = z;
            __threadfence();
            g_flag[b] = 1;
        }
    }
    __syncthreads();

    if (t < b) {
        while (g_flag[t] == 0) { }
        atomicAdd(&s_pref, g_agg[t]);
    }
    __syncthreads();
    int P = s_pref;

    if (i < n) {
        int start = P + warp_sum[w] + (x - v);
        g_start[i]  = start;
        g_cursor[i] = start;
        if (i == n - 1) g_start[n] = start + v;
    }
}

// 4 edges per thread, vectorized index/weight loads.
__global__ void k_scatter(const int4* __restrict__ esrc4,
                          const int4* __restrict__ edst4,
                          const float4* __restrict__ ew4,
                          int n_edges4) {
    int i = blockIdx.x * blockDim.x + threadIdx.x;
    if (i >= n_edges4) return;
    int4   s = __ldg(&esrc4[i]);
    int4   d = __ldg(&edst4[i]);
    float4 w = __ldg(&ew4[i]);
    int p0 = atomicAdd(&g_cursor[s.x], 1);
    int p1 = atomicAdd(&g_cursor[s.y], 1);
    int p2 = atomicAdd(&g_cursor[s.z], 1);
    int p3 = atomicAdd(&g_cursor[s.w], 1);
    g_edge[p0] = make_float2(__int_as_float(d.x), w.x);
    g_edge[p1] = make_float2(__int_as_float(d.y), w.y);
    g_edge[p2] = make_float2(__int_as_float(d.z), w.z);
    g_edge[p3] = make_float2(__int_as_float(d.w), w.w);
}

// 16 lanes per node, unroll-2 with next-pair prefetch; forced 8 blocks/SM.
__global__ __launch_bounds__(256, 8) void k_accum(const float* __restrict__ feat,
                                                  float* __restrict__ out,
                                                  int n_nodes) {
    int gid  = blockIdx.x * blockDim.x + threadIdx.x;
    int node = gid >> 4;
    int lane = gid & 15;
    if (node >= n_nodes) return;

    int beg = __ldg(&g_start[node]);
    int end = __ldg(&g_start[node + 1]);

    float4 acc = make_float4(0.f, 0.f, 0.f, 0.f);
    int j = beg;

    if (j + 1 < end) {
        // prime: load first pair
        float2 e0 = __ldg(&g_edge[j]);
        float2 e1 = __ldg(&g_edge[j + 1]);
        for (; j + 3 < end; j += 2) {
            // issue next pair's edge loads before consuming current gathers
            float2 n0 = __ldg(&g_edge[j + 2]);
            float2 n1 = __ldg(&g_edge[j + 3]);
            const float4* r0 = reinterpret_cast<const float4*>(feat + (__float_as_int(e0.x) << 6));
            const float4* r1 = reinterpret_cast<const float4*>(feat + (__float_as_int(e1.x) << 6));
            float4 v0 = __ldg(&r0[lane]);
            float4 v1 = __ldg(&r1[lane]);
            acc.x += v0.x * e0.y + v1.x * e1.y;
            acc.y += v0.y * e0.y + v1.y * e1.y;
            acc.z += v0.z * e0.y + v1.z * e1.y;
            acc.w += v0.w * e0.y + v1.w * e1.y;
            e0 = n0; e1 = n1;
        }
        // drain the in-flight pair
        const float4* r0 = reinterpret_cast<const float4*>(feat + (__float_as_int(e0.x) << 6));
        const float4* r1 = reinterpret_cast<const float4*>(feat + (__float_as_int(e1.x) << 6));
        float4 v0 = __ldg(&r0[lane]);
        float4 v1 = __ldg(&r1[lane]);
        acc.x += v0.x * e0.y + v1.x * e1.y;
        acc.y += v0.y * e0.y + v1.y * e1.y;
        acc.z += v0.z * e0.y + v1.z * e1.y;
        acc.w += v0.w * e0.y + v1.w * e1.y;
        j += 2;
    }
    if (j < end) {
        float2 e0 = __ldg(&g_edge[j]);
        const float4* r0 = reinterpret_cast<const float4*>(feat + (__float_as_int(e0.x) << 6));
        float4 v0 = __ldg(&r0[lane]);
        acc.x += v0.x * e0.y;
        acc.y += v0.y * e0.y;
        acc.z += v0.z * e0.y;
        acc.w += v0.w * e0.y;
    }
    reinterpret_cast<float4*>(out + ((long long)node << 6))[lane] = acc;
}

extern "C" void kernel_launch(void* const* d_in, const int* in_sizes, int n_in,
                              void* d_out, int out_size)
{
    const float* feat = (const float*)d_in[0];
    const float* ew   = (const float*)d_in[1];
    const int*   esrc = (const int*)d_in[2];
    const int*   edst = (const int*)d_in[3];
    float*       out  = (float*)d_out;

    int n_edges  = in_sizes[1];
    int n_nodes  = out_size / 64;
    int nb       = (n_nodes + SCAN_CHUNK - 1) / SCAN_CHUNK;   // 98
    int n_edges4 = n_edges / 4;                               // E divisible by 4

    k_hist<<<(n_edges4 + 255) / 256, 256>>>((const int4*)esrc, n_edges4);
    k_scan<<<nb, SCAN_CHUNK>>>(n_nodes);
    k_scatter<<<(n_edges4 + 255) / 256, 256>>>((const int4*)esrc, (const int4*)edst,
                                               (const float4*)ew, n_edges4);

    long long total = (long long)n_nodes * 16;
    k_accum<<<(int)((total + 255) / 256), 256>>>(feat, out, n_nodes);
}